// round 16
// baseline (speedup 1.0000x reference)
#include <cuda_runtime.h>
#include <math.h>

// Problem constants
#define N_POINTS 4096
#define N_VIEWS  4
#define IMG_H    128
#define IMG_W    128
#define N_PIX    (N_VIEWS * IMG_H * IMG_W)   // 65536
#define TOPK     5
#define R2F      0.0004f     // 0.02^2
#define CAP      40          // per-pixel hit capacity (max observed ~20)

#define NTHREADS 512
#define CLUSTER_CTAS 8
#define NBLOCKS  64          // 8 clusters x 8 CTAs; cluster = half a view (64 rows)

// cos(15deg), sin(15deg)
#define CE 0.96592582628906831f
#define SE 0.25881904510252074f

// Camera axes per view (columns of R): X_view = pcd . axis + T, T = (0,0,1.5)
__constant__ float c_ax[N_VIEWS][3] = {
    {-1.f, 0.f, 0.f}, {0.f, 0.f, 1.f}, {1.f, 0.f, 0.f}, {0.f, 0.f, -1.f}};
__constant__ float c_ay[N_VIEWS][3] = {
    {0.f, CE, -SE}, {-SE, CE, 0.f}, {0.f, CE, SE}, {SE, CE, 0.f}};
__constant__ float c_az[N_VIEWS][3] = {
    {0.f, -SE, -CE}, {-CE, -SE, 0.f}, {0.f, -SE, CE}, {CE, -SE, 0.f}};

// Plane-major per-pixel hit lists: hit j of pixel p at g_hits[j][p].
__device__ float4 g_hits[CAP][N_PIX];
__device__ int    g_hcnt[N_PIX];   // zero-init at load; reset in phase 2

__global__ void __launch_bounds__(NTHREADS) __cluster_dims__(CLUSTER_CTAS, 1, 1)
fused_kernel(const float* __restrict__ pcd,
             const float* __restrict__ displace,
             const float* __restrict__ init_colors,
             float* __restrict__ out) {
    const int tid = threadIdx.x;
    const int v   = blockIdx.x >> 4;          // view (16 CTAs per view)
    const int hh  = (blockIdx.x >> 3) & 1;    // half: rows [hh*64, hh*64+64)
    const int r   = blockIdx.x & 7;           // CTA rank within cluster
    const int rowlo = hh * 64;
    const int rowhi = rowlo + 63;

    // ---------------- Phase 1: transform ALL points for this view, ------------
    // ----------------          scatter hits landing in our 64-row half --------
    {
        int n = r * NTHREADS + tid;           // 0..4095: every point, once per cluster
        float x = pcd[3 * n + 0];
        float y = pcd[3 * n + 1];
        float z = pcd[3 * n + 2];
        float col = 1.0f / (1.0f + expf(-(init_colors[n] + displace[n])));
        if (v == 0 && hh == 0)
            out[(size_t)N_PIX * 3 + n] = col;   // colors_ tail (cluster 0 only)

        float px = x * c_ax[v][0] + y * c_ax[v][1] + z * c_ax[v][2];
        float py = x * c_ay[v][0] + y * c_ay[v][1] + z * c_ay[v][2];
        float zv = x * c_az[v][0] + y * c_az[v][1] + z * c_az[v][2] + 1.5f;
        float pz = (zv - 0.01f) / 99.99f;

        if (pz > 0.0f) {
            // pixel-center bbox: xf(xi) = 1 - (2xi+1)/128; disk spans <= 3 centers/axis
            const float rexp = 0.0201f;
            int ilo = max(0,     (int)ceilf ((1.0f - px - rexp) * 64.0f - 0.5f));
            int ihi = min(127,   (int)floorf((1.0f - px + rexp) * 64.0f - 0.5f));
            int jlo = max(rowlo, (int)ceilf ((1.0f - py - rexp) * 64.0f - 0.5f));
            int jhi = min(rowhi, (int)floorf((1.0f - py + rexp) * 64.0f - 0.5f));

            if (ilo <= ihi && jlo <= jhi) {
                const float inv128 = 0.0078125f;
                int   pp[9];
                float aa[9];
                bool  ok[9];
#pragma unroll
                for (int dj = 0; dj < 3; dj++) {
                    int yi = jlo + dj;
                    float yf = 1.0f - (float)(2 * yi + 1) * inv128;
                    float dy = py - yf;
                    float dy2 = dy * dy;
#pragma unroll
                    for (int di = 0; di < 3; di++) {
                        int e = dj * 3 + di;
                        int xi = ilo + di;
                        float xf = 1.0f - (float)(2 * xi + 1) * inv128;
                        float dx = px - xf;
                        float d2 = fmaf(dx, dx, dy2);
                        ok[e] = (yi <= jhi) && (xi <= ihi) && (d2 < R2F);
                        pp[e] = ((v * IMG_H) + yi) * IMG_W + xi;
                        aa[e] = 1.0f - d2 / R2F;
                    }
                }
                int ss[9];
#pragma unroll
                for (int e = 0; e < 9; e++)
                    ss[e] = ok[e] ? atomicAdd(&g_hcnt[pp[e]], 1) : CAP;
#pragma unroll
                for (int e = 0; e < 9; e++)
                    if (ss[e] < CAP)
                        g_hits[ss[e]][pp[e]] = make_float4(pz, aa[e], col, 0.0f);
            }
        }
    }

    // ---------------- Cluster barrier (HW, release/acquire semantics) ---------
    asm volatile("barrier.cluster.arrive.aligned;" ::: "memory");
    asm volatile("barrier.cluster.wait.aligned;"   ::: "memory");

    // ---------------- Phase 2: 2 pixels per thread, gather + top-5 + composite
    const int q  = r * NTHREADS + tid;              // 0..4095 local pair index
    const int p0 = v * (IMG_H * IMG_W) + rowlo * IMG_W + q * 2;
    const int p1 = p0 + 1;

    // 4 independent loads (counts + plane-0 hits), one latency round
    int n0 = g_hcnt[p0];
    int n1 = g_hcnt[p1];
    float4 h00 = g_hits[0][p0];
    float4 h01 = g_hits[0][p1];
    g_hcnt[p0] = 0;                // reset for next graph replay
    g_hcnt[p1] = 0;
    if (n0 > CAP) n0 = CAP;
    if (n1 > CAP) n1 = CAP;

    const float INF = __int_as_float(0x7f800000);
    float pixv[2];
#pragma unroll
    for (int px2 = 0; px2 < 2; px2++) {
        int n      = (px2 == 0) ? n0 : n1;
        float4 h0  = (px2 == 0) ? h00 : h01;
        int p      = (px2 == 0) ? p0 : p1;

        float zk[TOPK], ak[TOPK], ck[TOPK];
#pragma unroll
        for (int k = 0; k < TOPK; k++) { zk[k] = INF; ak[k] = 0.0f; ck[k] = 0.0f; }
        if (n > 0) { zk[0] = h0.x; ak[0] = h0.y; ck[0] = h0.z; }

#pragma unroll 2
        for (int j = 1; j < n; j++) {
            float4 h = g_hits[j][p];
            float nz = h.x, na = h.y, nc = h.z;
#pragma unroll
            for (int k = 0; k < TOPK; k++) {
                if (nz < zk[k]) {
                    float t;
                    t = zk[k]; zk[k] = nz; nz = t;
                    t = ak[k]; ak[k] = na; na = t;
                    t = ck[k]; ck[k] = nc; nc = t;
                }
            }
        }

        float trans = 1.0f, acc = 0.0f;
#pragma unroll
        for (int k = 0; k < TOPK; k++) {
            acc += ak[k] * trans * ck[k];
            trans *= (1.0f - ak[k]);
        }
        pixv[px2] = acc;
    }

    // 6 contiguous floats starting at 3*p0
    int base = p0 * 3;
    out[base + 0] = pixv[0];
    out[base + 1] = pixv[0];
    out[base + 2] = pixv[0];
    out[base + 3] = pixv[1];
    out[base + 4] = pixv[1];
    out[base + 5] = pixv[1];
}

extern "C" void kernel_launch(void* const* d_in, const int* in_sizes, int n_in,
                              void* d_out, int out_size) {
    const float* pcd         = (const float*)d_in[0];
    const float* displace    = (const float*)d_in[1];
    const float* init_colors = (const float*)d_in[2];
    float* out = (float*)d_out;

    fused_kernel<<<NBLOCKS, NTHREADS>>>(pcd, displace, init_colors, out);
}

// round 17
// speedup vs baseline: 1.1544x; 1.1544x over previous
#include <cuda_runtime.h>
#include <math.h>

// Problem constants
#define N_POINTS 4096
#define N_VIEWS  4
#define IMG_H    128
#define IMG_W    128
#define N_PIX    (N_VIEWS * IMG_H * IMG_W)   // 65536
#define TOPK     5
#define R2F      0.0004f     // 0.02^2
#define CAP      40          // per-pixel hit capacity (max observed ~20)

// cos(15deg), sin(15deg)
#define CE 0.96592582628906831f
#define SE 0.25881904510252074f

// Camera axes per view (columns of R): X_view = pcd . axis + T, T = (0,0,1.5)
__constant__ float c_ax[N_VIEWS][3] = {
    {-1.f, 0.f, 0.f}, {0.f, 0.f, 1.f}, {1.f, 0.f, 0.f}, {0.f, 0.f, -1.f}};
__constant__ float c_ay[N_VIEWS][3] = {
    {0.f, CE, -SE}, {-SE, CE, 0.f}, {0.f, CE, SE}, {SE, CE, 0.f}};
__constant__ float c_az[N_VIEWS][3] = {
    {0.f, -SE, -CE}, {-CE, -SE, 0.f}, {0.f, -SE, CE}, {CE, -SE, 0.f}};

// Plane-major per-pixel hit lists: hit j of pixel p at g_hits[j][p].
__device__ float4 g_hits[CAP][N_PIX];
__device__ int    g_hcnt[N_PIX];      // zero-init at load; raster resets after read

// One thread per (point, view). 4 consecutive threads share a point.
__global__ void __launch_bounds__(128)
prep_kernel(const float* __restrict__ pcd,
            const float* __restrict__ displace,
            const float* __restrict__ init_colors,
            float* __restrict__ out_colors) {
    int t = blockIdx.x * blockDim.x + threadIdx.x;
    int n = t >> 2;
    int v = t & 3;

    float x = pcd[3 * n + 0];
    float y = pcd[3 * n + 1];
    float z = pcd[3 * n + 2];
    // fast sigmoid: __expf (MUFU) — ~1e-6 rel error, 1000x below threshold
    float col = 1.0f / (1.0f + __expf(-(init_colors[n] + displace[n])));
    if (v == 0) out_colors[n] = col;

    float px = x * c_ax[v][0] + y * c_ax[v][1] + z * c_ax[v][2];
    float py = x * c_ay[v][0] + y * c_ay[v][1] + z * c_ay[v][2];
    float zv = x * c_az[v][0] + y * c_az[v][1] + z * c_az[v][2] + 1.5f;
    float pz = (zv - 0.01f) / 99.99f;
    if (pz <= 0.0f) return;

    // pixel-center bbox: xf(xi) = 1 - (2xi+1)/128; disk spans <= 3 centers/axis
    const float rexp = 0.0201f;
    int ilo = max(0,   (int)ceilf ((1.0f - px - rexp) * 64.0f - 0.5f));
    int ihi = min(127, (int)floorf((1.0f - px + rexp) * 64.0f - 0.5f));
    int jlo = max(0,   (int)ceilf ((1.0f - py - rexp) * 64.0f - 0.5f));
    int jhi = min(127, (int)floorf((1.0f - py + rexp) * 64.0f - 0.5f));

    const float inv128 = 0.0078125f;

    // Fully unrolled 3x3 predicated scatter: 9 independent tests,
    // independent atomics issued back-to-back (latency overlapped).
    int   pp[9];
    float aa[9];
    bool  ok[9];
#pragma unroll
    for (int dj = 0; dj < 3; dj++) {
        int yi = jlo + dj;
        float yf = 1.0f - (float)(2 * yi + 1) * inv128;
        float dy = py - yf;
        float dy2 = dy * dy;
#pragma unroll
        for (int di = 0; di < 3; di++) {
            int e = dj * 3 + di;
            int xi = ilo + di;
            float xf = 1.0f - (float)(2 * xi + 1) * inv128;
            float dx = px - xf;
            float d2 = fmaf(dx, dx, dy2);
            ok[e] = (yi <= jhi) && (xi <= ihi) && (d2 < R2F);
            pp[e] = ((v * IMG_H) + yi) * IMG_W + xi;
            aa[e] = 1.0f - d2 / R2F;
        }
    }
    int ss[9];
#pragma unroll
    for (int e = 0; e < 9; e++)
        ss[e] = ok[e] ? atomicAdd(&g_hcnt[pp[e]], 1) : CAP;
#pragma unroll
    for (int e = 0; e < 9; e++)
        if (ss[e] < CAP)
            g_hits[ss[e]][pp[e]] = make_float4(pz, aa[e], col, 0.0f);
}

// One thread per pixel: count + hit planes 0,1 prefetched concurrently
// (one latency round covers ~99% of pixels), top-5 by z, over-composite.
__global__ void __launch_bounds__(128) raster_kernel(float* __restrict__ out) {
    const int p = blockIdx.x * 128 + threadIdx.x;

    // three independent loads, single latency round
    int n = g_hcnt[p];
    float4 h0 = g_hits[0][p];
    float4 h1 = g_hits[1][p];
    g_hcnt[p] = 0;                 // reset for next graph replay (same thread: ordered)
    if (n > CAP) n = CAP;

    const float INF = __int_as_float(0x7f800000);
    float zk[TOPK], ak[TOPK], ck[TOPK];
#pragma unroll
    for (int k = 0; k < TOPK; k++) { zk[k] = INF; ak[k] = 0.0f; ck[k] = 0.0f; }

    if (n > 0) { zk[0] = h0.x; ak[0] = h0.y; ck[0] = h0.z; }
    if (n > 1) {
        // insert h1 into the 1-element list
        if (h1.x < zk[0]) {
            zk[1] = zk[0]; ak[1] = ak[0]; ck[1] = ck[0];
            zk[0] = h1.x;  ak[0] = h1.y;  ck[0] = h1.z;
        } else {
            zk[1] = h1.x;  ak[1] = h1.y;  ck[1] = h1.z;
        }
    }

    // remaining hits (rare: ~1% of pixels)
    for (int j = 2; j < n; j++) {
        float4 h = g_hits[j][p];
        float nz = h.x, na = h.y, nc = h.z;
#pragma unroll
        for (int k = 0; k < TOPK; k++) {
            if (nz < zk[k]) {
                float t;
                t = zk[k]; zk[k] = nz; nz = t;
                t = ak[k]; ak[k] = na; na = t;
                t = ck[k]; ck[k] = nc; nc = t;
            }
        }
    }

    // front-to-back over-composite (empty slots contribute 0)
    float trans = 1.0f, pixv = 0.0f;
#pragma unroll
    for (int k = 0; k < TOPK; k++) {
        pixv += ak[k] * trans * ck[k];
        trans *= (1.0f - ak[k]);
    }

    int base = p * 3;
    out[base + 0] = pixv;
    out[base + 1] = pixv;
    out[base + 2] = pixv;
}

extern "C" void kernel_launch(void* const* d_in, const int* in_sizes, int n_in,
                              void* d_out, int out_size) {
    const float* pcd         = (const float*)d_in[0];
    const float* displace    = (const float*)d_in[1];
    const float* init_colors = (const float*)d_in[2];
    float* out = (float*)d_out;

    // colors_ tail lives after the 4*128*128*3 image block
    float* out_colors = out + (size_t)N_PIX * 3;

    prep_kernel<<<N_POINTS * N_VIEWS / 128, 128>>>(pcd, displace, init_colors, out_colors);
    raster_kernel<<<N_PIX / 128, 128>>>(out);
}